// round 8
// baseline (speedup 1.0000x reference)
#include <cuda_runtime.h>

// ---------------------------------------------------------------------------
// VQ-VAE: nearest-code search + z_q gather + commitment loss + EMA update.
// Bit-exact emulation of the reference distance rounding (DO NOT CHANGE):
//   u_k = fl( fl(z_sq - 2*dot_k) + e_sq_k );  key = fl(sqrt(max(u_k,0)))
//   argmin over key, first-index tie-break.
// z_sq / e_sq use XLA-CPU SIMD reduce-of-8 order (stride-4 chunk + halving
// tree):  v_j = s_j + s_{j+4};  sum = (v0+v2) + (v1+v3)
// V=4 vectors/thread (amortize codebook LDS + float4 global I/O).
// ---------------------------------------------------------------------------

#define KCODES   512
#define DIM      8
#define HW       4096
#define NVEC     (64 * HW)
#define TPB      128
#define VPT      4
#define NBLK     (NVEC / (TPB * VPT))   // 512
#define CSTRIDE  4096
#define BSTRIDE  (DIM * HW)

#define OUT_ZQ   0
#define OUT_LOSS 2097152
#define OUT_CB   2097153
#define OUT_CS   (2097153 + 4096)
#define OUT_W    (2097153 + 4096 + 512)

// scratch (zero at module load; finalize re-zeros each call for graph replay)
__device__ float g_counts[KCODES];
__device__ float g_sums[KCODES * DIM];
__device__ float g_loss;
__device__ int   g_done;

// -------- packed f32x2 helpers ---------------------------------------------
__device__ __forceinline__ unsigned long long pack2(float lo, float hi) {
    unsigned long long r;
    asm("mov.b64 %0, {%1, %2};" : "=l"(r) : "f"(lo), "f"(hi));
    return r;
}
__device__ __forceinline__ void unpack2(unsigned long long v, float& lo, float& hi) {
    asm("mov.b64 {%0, %1}, %2;" : "=f"(lo), "=f"(hi) : "l"(v));
}
__device__ __forceinline__ unsigned long long fma2(unsigned long long a,
                                                   unsigned long long b,
                                                   unsigned long long c) {
    unsigned long long d;
    asm("fma.rn.f32x2 %0, %1, %2, %3;" : "=l"(d) : "l"(a), "l"(b), "l"(c));
    return d;
}
__device__ __forceinline__ unsigned long long add2(unsigned long long a,
                                                   unsigned long long b) {
    unsigned long long d;
    asm("add.rn.f32x2 %0, %1, %2;" : "=l"(d) : "l"(a), "l"(b));
    return d;
}
__device__ __forceinline__ void lds2x64(unsigned addr, unsigned long long& a,
                                        unsigned long long& b) {
    asm volatile("ld.shared.v2.b64 {%0, %1}, [%2];"
                 : "=l"(a), "=l"(b) : "r"(addr));
}
__device__ __forceinline__ unsigned long long lds64(unsigned addr) {
    unsigned long long v;
    asm volatile("ld.shared.b64 %0, [%1];" : "=l"(v) : "r"(addr));
    return v;
}

// XLA-CPU SIMD sum of 8 squares: stride-4 chunk, then halving tree. (pinned)
__device__ __forceinline__ float sumsq8(const float* x) {
    float s[DIM];
#pragma unroll
    for (int d = 0; d < DIM; d++) s[d] = __fmul_rn(x[d], x[d]);
    float v0 = __fadd_rn(s[0], s[4]);
    float v1 = __fadd_rn(s[1], s[5]);
    float v2 = __fadd_rn(s[2], s[6]);
    float v3 = __fadd_rn(s[3], s[7]);
    return __fadd_rn(__fadd_rn(v0, v2), __fadd_rn(v1, v3));
}

// ---------------------------------------------------------------------------
__global__ __launch_bounds__(TPB, 3)
void vq_fused(const float* __restrict__ z, const float* __restrict__ cb,
              const float* __restrict__ ema_cs, const float* __restrict__ ema_w,
              float* __restrict__ out) {
    // pair layout: sh_pair[kp*8 + d] = {e[2kp][d], e[2kp+1][d]}
    __shared__ __align__(16) float2 sh_pair[(KCODES / 2) * DIM];  // 16 KB
    __shared__ __align__(16) float  sh_e2[KCODES];                //  2 KB
    __shared__ float sh_cnt[KCODES];                              //  2 KB
    __shared__ float sh_sum[KCODES * DIM];                        // 16 KB
    __shared__ float sh_loss;
    __shared__ int   sh_last;
    __shared__ float sh_n;

    const int tid = threadIdx.x;
    float* sp = (float*)sh_pair;

    // ---- prologue ----
    for (int i = tid; i < KCODES * DIM; i += TPB) {
        int k = i >> 3, d = i & 7;
        sp[(((k >> 1) << 3) + d) * 2 + (k & 1)] = cb[i];
    }
    for (int k = tid; k < KCODES; k += TPB) {
        float e[DIM];
#pragma unroll
        for (int d = 0; d < DIM; d++) e[d] = cb[k * DIM + d];
        sh_e2[k] = sumsq8(e);
    }
    for (int i = tid; i < KCODES; i += TPB) sh_cnt[i] = 0.f;
    for (int i = tid; i < KCODES * DIM; i += TPB) sh_sum[i] = 0.f;
    if (tid == 0) sh_loss = 0.f;
    __syncthreads();

    // ---- this thread's 4 consecutive vectors ----
    const int vi = (blockIdx.x * TPB + tid) * VPT;   // multiple of 4
    const int b0 = vi >> 12, n0 = vi & 4095;         // all 4 in same batch item
    const float* zp = z + b0 * BSTRIDE + n0;

    // Load z (float4 per dim), compute z_sq (pinned), pack -2z.
    unsigned long long zz[VPT][DIM];
    unsigned long long zsq2[VPT];
    {
        float za[VPT][DIM];
#pragma unroll
        for (int d = 0; d < DIM; d++) {
            float4 q = *(const float4*)(zp + d * CSTRIDE);
            za[0][d] = q.x; za[1][d] = q.y; za[2][d] = q.z; za[3][d] = q.w;
        }
#pragma unroll
        for (int v = 0; v < VPT; v++) {
            float zs = sumsq8(za[v]);
            zsq2[v] = pack2(zs, zs);
#pragma unroll
            for (int d = 0; d < DIM; d++) {
                float a = __fmul_rn(-2.0f, za[v][d]);   // exact
                zz[v][d] = pack2(a, a);
            }
        }
    }
    const unsigned long long zero2 = pack2(0.f, 0.f);

    const unsigned pbase = (unsigned)__cvta_generic_to_shared(sh_pair);
    const unsigned hbase = (unsigned)__cvta_generic_to_shared(sh_e2);

    float m1[VPT], m2[VPT];
    int i1[VPT];
#pragma unroll
    for (int v = 0; v < VPT; v++) { m1[v] = 3.4e38f; m2[v] = 3.4e38f; i1[v] = 0; }

    // ---- main search loop: one codebook LDS burst serves 4 vectors ----
    for (int kp = 0; kp < KCODES / 2; kp++) {
        unsigned addr = pbase + kp * 64;
        unsigned long long e[DIM];
        lds2x64(addr,      e[0], e[1]);
        lds2x64(addr + 16, e[2], e[3]);
        lds2x64(addr + 32, e[4], e[5]);
        lds2x64(addr + 48, e[6], e[7]);
        unsigned long long ep = lds64(hbase + kp * 8);

        unsigned long long acc[VPT];
#pragma unroll
        for (int v = 0; v < VPT; v++) acc[v] = zero2;
#pragma unroll
        for (int i = 0; i < DIM; i++) {
#pragma unroll
            for (int v = 0; v < VPT; v++) acc[v] = fma2(zz[v][i], e[i], acc[v]);
        }
#pragma unroll
        for (int v = 0; v < VPT; v++) {
            unsigned long long u2 = add2(add2(zsq2[v], acc[v]), ep);
            float u0, u1;
            unpack2(u2, u0, u1);
            {
                bool p = u0 < m1[v];
                float t = fmaxf(m1[v], u0);
                m2[v] = fminf(m2[v], t);
                m1[v] = fminf(m1[v], u0);
                i1[v] = p ? 2 * kp : i1[v];
            }
            {
                bool p = u1 < m1[v];
                float t = fmaxf(m1[v], u1);
                m2[v] = fminf(m2[v], t);
                m1[v] = fminf(m1[v], u1);
                i1[v] = p ? 2 * kp + 1 : i1[v];
            }
        }
    }

    // recover z exactly: z[d] = -0.5 * (-2 z[d])
    float za[VPT][DIM], zsq[VPT];
#pragma unroll
    for (int v = 0; v < VPT; v++) {
        float lo, hi;
#pragma unroll
        for (int d = 0; d < DIM; d++) {
            unpack2(zz[v][d], lo, hi);
            za[v][d] = -0.5f * lo;
        }
        unpack2(zsq2[v], lo, hi);
        zsq[v] = lo;
    }

    // ---- sqrt tie resolution (rare): first index whose KEY == min key ----
    int bi[VPT];
#pragma unroll
    for (int v = 0; v < VPT; v++) {
        bi[v] = i1[v];
        if (__fsqrt_rn(fmaxf(m2[v], 0.f)) == __fsqrt_rn(fmaxf(m1[v], 0.f))) {
            float q1 = __fsqrt_rn(fmaxf(m1[v], 0.f));
            for (int k = 0; k < KCODES; k++) {
                float acc = 0.f;
#pragma unroll
                for (int d = 0; d < DIM; d++)
                    acc = __fmaf_rn(__fmul_rn(-2.0f, za[v][d]),
                                    sp[(((k >> 1) << 3) + d) * 2 + (k & 1)], acc);
                float u = __fadd_rn(__fadd_rn(zsq[v], acc), sh_e2[k]);
                if (__fsqrt_rn(fmaxf(u, 0.f)) == q1) { bi[v] = k; break; }
            }
        }
    }

    // ---- epilogue: z_q (float4 stores), loss, block histogram ----
    float lsum = 0.f;
    float* outp = out + OUT_ZQ + b0 * BSTRIDE + n0;
#pragma unroll
    for (int d = 0; d < DIM; d++) {
        float4 q;
        float e0 = sp[(((bi[0] >> 1) << 3) + d) * 2 + (bi[0] & 1)];
        float e1 = sp[(((bi[1] >> 1) << 3) + d) * 2 + (bi[1] & 1)];
        float e2v = sp[(((bi[2] >> 1) << 3) + d) * 2 + (bi[2] & 1)];
        float e3 = sp[(((bi[3] >> 1) << 3) + d) * 2 + (bi[3] & 1)];
        q.x = e0; q.y = e1; q.z = e2v; q.w = e3;
        *(float4*)(outp + d * CSTRIDE) = q;
        float d0 = e0 - za[0][d], d1 = e1 - za[1][d];
        float d2 = e2v - za[2][d], d3 = e3 - za[3][d];
        lsum += d0 * d0 + d1 * d1 + d2 * d2 + d3 * d3;
    }
#pragma unroll
    for (int v = 0; v < VPT; v++) {
#pragma unroll
        for (int d = 0; d < DIM; d++) atomicAdd(&sh_sum[bi[v] * DIM + d], za[v][d]);
        atomicAdd(&sh_cnt[bi[v]], 1.f);
    }
    atomicAdd(&sh_loss, lsum);
    __syncthreads();

    // ---- flush block histogram to global ----
    for (int i = tid; i < KCODES; i += TPB) {
        float c = sh_cnt[i];
        if (c != 0.f) atomicAdd(&g_counts[i], c);
    }
    for (int i = tid; i < KCODES * DIM; i += TPB) {
        float s = sh_sum[i];
        if (s != 0.f) atomicAdd(&g_sums[i], s);
    }
    if (tid == 0) atomicAdd(&g_loss, sh_loss);

    // ---- last-block EMA finalize ----
    __threadfence();
    __syncthreads();
    if (tid == 0) sh_last = (atomicAdd(&g_done, 1) == NBLK - 1);
    __syncthreads();
    if (!sh_last) return;

    float ncs_l[KCODES / TPB];
#pragma unroll
    for (int j = 0; j < KCODES / TPB; j++) {
        int k = tid + j * TPB;
        float ncs = ema_cs[k] * 0.99f + __ldcg(&g_counts[k]) * 0.01f;
        ncs_l[j] = ncs;
        sh_cnt[k] = ncs;
    }
    __syncthreads();
    if (tid < 64) {
        float s = 0.f;
#pragma unroll
        for (int j = 0; j < 8; j++) s += sh_cnt[tid * 8 + j];
        sh_sum[tid] = s;
    }
    __syncthreads();
    if (tid == 0) {
        float s = 0.f;
        for (int i = 0; i < 64; i++) s += sh_sum[i];
        sh_n = s;
        out[OUT_LOSS] = __ldcg(&g_loss) * (1.0f / 2097152.0f);
        g_loss = 0.f;
        g_done = 0;
    }
    __syncthreads();
    const float n = sh_n;
#pragma unroll
    for (int j = 0; j < KCODES / TPB; j++) {
        int k = tid + j * TPB;
        float cs = (ncs_l[j] + 1e-5f) / (n + KCODES * 1e-5f) * n;
        out[OUT_CS + k] = cs;
        float inv = 1.0f / cs;
#pragma unroll
        for (int d = 0; d < DIM; d++) {
            float nw = ema_w[k * DIM + d] * 0.99f + __ldcg(&g_sums[k * DIM + d]) * 0.01f;
            out[OUT_W + k * DIM + d] = nw;
            out[OUT_CB + k * DIM + d] = nw * inv;
            g_sums[k * DIM + d] = 0.f;
        }
        g_counts[k] = 0.f;
    }
}

// ---------------------------------------------------------------------------
extern "C" void kernel_launch(void* const* d_in, const int* in_sizes, int n_in,
                              void* d_out, int out_size) {
    const float* z      = (const float*)d_in[0];
    const float* cb     = (const float*)d_in[1];
    const float* ema_cs = (const float*)d_in[2];
    const float* ema_w  = (const float*)d_in[3];
    float* out = (float*)d_out;

    vq_fused<<<NBLK, TPB>>>(z, cb, ema_cs, ema_w, out);
}